// round 7
// baseline (speedup 1.0000x reference)
#include <cuda_runtime.h>
#include <math.h>

// Input order:
// 0 poi_idx(i32 B*N) 1 hour_of_week(i32 B*N) 2 lat 3 lon 4 t_min (f32 B*N)
// 5 region_centroids(R*2) 6 poi_emb((N_POIS+1)*D) 7 time_emb(169*D)
// 8 E_t(64) 9 E_d(64) 10 E_d_match(64) 11 region_emb(R*D) 12 Wq 13 Wk 14 Wv (D*D)
// output: f32 (B, R) = (1024, 1000)

#define BB 1024
#define NN 50
#define RR 1000
#define DD 128
#define DEG2RADF 0.017453292519943295f
#define INV_SQRT_D 0.08838834764831845f   // 1/sqrt(128)

typedef unsigned long long u64;

// scratch
__device__ float g_S[BB * NN * DD];       // S = attn @ V, [b][n][d]
__device__ float g_M[DD * DD];            // M[b][a] = sum_j Wq[j][a]*Wk[j][b]

__device__ __forceinline__ u64 pk2(float lo, float hi) {
    u64 r; asm("mov.b64 %0, {%1, %2};" : "=l"(r) : "f"(lo), "f"(hi)); return r;
}
__device__ __forceinline__ void upk2(u64 v, float& lo, float& hi) {
    asm("mov.b64 {%0, %1}, %2;" : "=f"(lo), "=f"(hi) : "l"(v));
}
__device__ __forceinline__ u64 ffma2(u64 a, u64 b, u64 c) {
    u64 d; asm("fma.rn.f32x2 %0, %1, %2, %3;" : "=l"(d) : "l"(a), "l"(b), "l"(c)); return d;
}

__device__ __forceinline__ float interp64(const float* t, float x) {
    x = fminf(fmaxf(x, 0.0f), 62.999996f);
    int k = (int)x;
    float f = x - (float)k;
    return t[k] + f * (t[k + 1] - t[k]);
}

// sin(x) for |x| < 0.01 rad: x - x^3/6, abs err ~1e-12
__device__ __forceinline__ float sinp(float x) {
    float x2 = x * x;
    return x * fmaf(x2, -0.16666667f, 1.0f);
}

// haversine, asin series (all distances here < 160km so series is exact enough)
__device__ __forceinline__ float hav_km(float dlatr, float dlonr, float cc) {
    float s1 = sinp(0.5f * dlatr);
    float s2 = sinp(0.5f * dlonr);
    float a = fmaf(s1, s1, cc * s2 * s2);
    a = fminf(a, 1.0f);
    float w = sqrtf(a);
    return w * fmaf(2123.6667f, a, 12742.0f);
}

// ---------------- Kernel 0: M = Wq^T Wk  (stored transposed: g_M[b][a]) ----

__global__ void stan_k0(const float* __restrict__ Wq, const float* __restrict__ Wk) {
    int bcol = blockIdx.x;    // 0..127
    int a = threadIdx.x;      // 0..127
    float s0 = 0.f, s1 = 0.f, s2 = 0.f, s3 = 0.f;
#pragma unroll
    for (int j = 0; j < 128; j += 4) {
        s0 = fmaf(__ldg(&Wq[(j + 0) * 128 + a]), __ldg(&Wk[(j + 0) * 128 + bcol]), s0);
        s1 = fmaf(__ldg(&Wq[(j + 1) * 128 + a]), __ldg(&Wk[(j + 1) * 128 + bcol]), s1);
        s2 = fmaf(__ldg(&Wq[(j + 2) * 128 + a]), __ldg(&Wk[(j + 2) * 128 + bcol]), s2);
        s3 = fmaf(__ldg(&Wq[(j + 3) * 128 + a]), __ldg(&Wk[(j + 3) * 128 + bcol]), s3);
    }
    g_M[bcol * 128 + a] = (s0 + s1) + (s2 + s3);
}

// ---------------- Kernel 1: x, Y=xM^T, scores, V, softmax, S --------------

struct S1 {
    float xT[128][52];   // x transposed [d][n]
    float YT[128][52];   // y transposed [j][n]; reused as Vt after scores
    float P[50][52];     // scores -> attn [n][m]
    float Et[64];
    float Ed[64];
    float tmin_s[50];
    float latr[50];
    float lonr[50];
    float coslat[50];
    float validf[50];
    int   psafe[50];
    int   hsafe[50];
};

__device__ __forceinline__ void gemm_pass(const float (*xT)[52], float (*OT)[52],
                                          const float* __restrict__ W,
                                          int j0, int n0, int cnt) {
    u64 a0[7], a1[7];
#pragma unroll
    for (int k = 0; k < 7; k++) { a0[k] = 0ull; a1[k] = 0ull; }
    const float4* w0 = (const float4*)(W + j0 * 128);
    const float4* w1 = (const float4*)(W + (j0 + 1) * 128);
#pragma unroll 4
    for (int d4 = 0; d4 < 32; d4++) {
        float4 wa = __ldg(&w0[d4]);
        float4 wb = __ldg(&w1[d4]);
        float wav[4] = {wa.x, wa.y, wa.z, wa.w};
        float wbv[4] = {wb.x, wb.y, wb.z, wb.w};
#pragma unroll
        for (int dd = 0; dd < 4; dd++) {
            int d = 4 * d4 + dd;
            u64 p0 = pk2(wav[dd], wav[dd]);
            u64 p1 = pk2(wbv[dd], wbv[dd]);
#pragma unroll
            for (int k = 0; k < 7; k++) {
                u64 x2 = *(const u64*)&xT[d][n0 + 2 * k];
                a0[k] = ffma2(x2, p0, a0[k]);
                a1[k] = ffma2(x2, p1, a1[k]);
            }
        }
    }
#pragma unroll
    for (int k = 0; k < 7; k++) {
        if (k < cnt) {
            *(u64*)&OT[j0][n0 + 2 * k]     = a0[k];
            *(u64*)&OT[j0 + 1][n0 + 2 * k] = a1[k];
        }
    }
}

__global__ void __launch_bounds__(256, 3)
stan_k1(const int* __restrict__ poi_idx, const int* __restrict__ hour,
        const float* __restrict__ lat, const float* __restrict__ lon,
        const float* __restrict__ tmin,
        const float* __restrict__ poi_emb, const float* __restrict__ time_emb,
        const float* __restrict__ E_t, const float* __restrict__ E_d,
        const float* __restrict__ Wv) {
    extern __shared__ char smraw[];
    S1* sm = (S1*)smraw;
    const int b = blockIdx.x;
    const int t = threadIdx.x;

    if (t < 50) {
        int pi = poi_idx[b * 50 + t];
        bool pad = pi < 0;
        sm->psafe[t] = pad ? 50000 : pi;
        sm->hsafe[t] = pad ? 0 : hour[b * 50 + t];
        sm->validf[t] = pad ? 0.0f : 1.0f;
        float la = lat[b * 50 + t] * DEG2RADF;
        float lo = lon[b * 50 + t] * DEG2RADF;
        sm->latr[t] = la; sm->lonr[t] = lo;
        sm->coslat[t] = cosf(la);
        sm->tmin_s[t] = tmin[b * 50 + t];
    }
    if (t >= 64 && t < 128) { sm->Et[t - 64] = E_t[t - 64]; sm->Ed[t - 64] = E_d[t - 64]; }
    __syncthreads();

    for (int idx = t; idx < 50 * 128; idx += 256) {
        int n = idx >> 7, d = idx & 127;
        sm->xT[d][n] = poi_emb[sm->psafe[n] * 128 + d] + time_emb[sm->hsafe[n] * 128 + d];
    }
    __syncthreads();

    const int jp = t & 63;
    const int qtr = t >> 6;
    const int j0 = 2 * jp;
    const int n0tab[4] = {0, 14, 26, 38};
    const int cnttab[4] = {7, 6, 6, 6};
    const int n0 = n0tab[qtr];
    const int cnt = cnttab[qtr];

    // Y = x M^T   (scores = Y x^T)
    gemm_pass(sm->xT, sm->YT, g_M, j0, n0, cnt);
    __syncthreads();

    // scores
    for (int q = t; q < 1250; q += 256) {
        int np = q / 50, m = q - np * 50;
        int n = 2 * np;
        u64 acc = 0ull;
#pragma unroll 16
        for (int d = 0; d < 128; d++) {
            float xv = sm->xT[d][m];
            acc = ffma2(*(const u64*)&sm->YT[d][n], pk2(xv, xv), acc);
        }
        float lo, hi; upk2(acc, lo, hi);
        float vm = sm->validf[m];
        float ltm = sm->latr[m], lnm = sm->lonr[m], clm = sm->coslat[m], tm = sm->tmin_s[m];
#pragma unroll
        for (int u = 0; u < 2; u++) {
            int nn = n + u;
            float dotv = u ? hi : lo;
            float vp = sm->validf[nn] * vm;
            float dtm = fabsf(sm->tmin_s[nn] - tm) * vp;
            float dd = hav_km(ltm - sm->latr[nn], lnm - sm->lonr[nn],
                              sm->coslat[nn] * clm) * vp;
            float s = dotv * INV_SQRT_D
                    + interp64(sm->Et, fminf(dtm, 10080.0f) * 0.00625f)
                    + interp64(sm->Ed, fminf(dd, 200.0f) * 0.315f);
            sm->P[nn][m] = (vm != 0.0f) ? s : -1.0e30f;
        }
    }
    __syncthreads();

    // V pass (overwrites YT as Vt[j][m-pairs])
    gemm_pass(sm->xT, sm->YT, Wv, j0, n0, cnt);

    // row softmax
    if (t < 50) {
        float mx = -3.0e38f;
#pragma unroll
        for (int m = 0; m < 50; m++) mx = fmaxf(mx, sm->P[t][m]);
        if (mx <= -9.0e29f) {
            for (int m = 0; m < 50; m++) sm->P[t][m] = 0.0f;
        } else {
            float sum = 0.0f;
#pragma unroll
            for (int m = 0; m < 50; m++) {
                float e = __expf(sm->P[t][m] - mx);
                sm->P[t][m] = e; sum += e;
            }
            float inv = 1.0f / sum;
#pragma unroll
            for (int m = 0; m < 50; m++) sm->P[t][m] *= inv;
        }
    }
    __syncthreads();

    // S = attn @ V
    float (*Vt)[52] = sm->YT;
    const int nrows = 2 * cnt;
    for (int nn = 0; nn < nrows; nn++) {
        int n = n0 + nn;
        u64 acc0 = 0ull, acc1 = 0ull;
#pragma unroll
        for (int i = 0; i < 25; i++) {
            u64 a2 = *(const u64*)&sm->P[n][2 * i];
            acc0 = ffma2(a2, *(const u64*)&Vt[j0][2 * i], acc0);
            acc1 = ffma2(a2, *(const u64*)&Vt[j0 + 1][2 * i], acc1);
        }
        float l0, h0, l1, h1; upk2(acc0, l0, h0); upk2(acc1, l1, h1);
        *(float2*)&g_S[(b * 50 + n) * 128 + j0] = make_float2(l0 + h0, l1 + h1);
    }
}

// ---------------- Kernel 2: m_scores GEMM + column softmax ----------------
// block = 256 threads: h = t>>6 (4-way n-split, 7 pairs each, pairs 0..27),
// rq = t&63; thread owns r = rbase + rq + 64*i, i=0..3 (strided, conflict-free).
// No max-tracking softmax: scores are bounded; masked entries -> exp = 0.

struct S2 {
    float sS[128][58];      // S transposed [d][n], cols 50..57 zero
    float tile[256][37];    // Remb chunk [row][d-local], pad 37 (bank-clean)
    float slat[56], slon[56], scos[56], sval[56];
    float Edm[64];
    float red[4][64][8];    // per-h partials: (den,num) x 4 r
};

__global__ void __launch_bounds__(256, 2)
stan_k2(const int* __restrict__ poi_idx, const float* __restrict__ lat,
        const float* __restrict__ lon, const float* __restrict__ cent,
        const float* __restrict__ E_dm, const float* __restrict__ Remb,
        float* __restrict__ out) {
    extern __shared__ char smraw[];
    S2* sm = (S2*)smraw;
    const int b = blockIdx.y;
    const int rbase = blockIdx.x * 256;
    const int t = threadIdx.x;
    const int rq = t & 63;
    const int h = t >> 6;
    const int KLO = 7 * h;           // pairs [7h, 7h+7)

    if (t < 50) {
        sm->sval[t] = (poi_idx[b * 50 + t] < 0) ? 0.0f : 1.0f;
        float la = lat[b * 50 + t] * DEG2RADF;
        float lo = lon[b * 50 + t] * DEG2RADF;
        sm->slat[t] = la; sm->slon[t] = lo; sm->scos[t] = cosf(la);
    }
    if (t >= 50 && t < 56) { sm->sval[t] = 0.0f; sm->slat[t] = 0.0f; sm->slon[t] = 0.0f; sm->scos[t] = 1.0f; }
    if (t >= 64 && t < 128) sm->Edm[t - 64] = E_dm[t - 64];
    if (t < 128) {
#pragma unroll
        for (int c = 50; c < 58; c++) sm->sS[t][c] = 0.0f;
    }
    for (int idx = t; idx < 50 * 128; idx += 256) {
        int n = idx >> 7, d = idx & 127;
        sm->sS[d][n] = g_S[b * 6400 + idx];
    }

    u64 acc[4][7];
#pragma unroll
    for (int i = 0; i < 4; i++)
#pragma unroll
        for (int k = 0; k < 7; k++) acc[i][k] = 0ull;

    for (int dc = 0; dc < 4; dc++) {
        __syncthreads();
        // stage Remb rows [rbase, rbase+256) x d [32dc, 32dc+32)
        for (int f = t; f < 2048; f += 256) {
            int row = f >> 3, fi = f & 7;
            int rr = rbase + row; if (rr > 999) rr = 999;
            float4 v = __ldg((const float4*)(Remb + (size_t)rr * 128 + dc * 32 + fi * 4));
            float* dst = &sm->tile[row][fi * 4];
            dst[0] = v.x; dst[1] = v.y; dst[2] = v.z; dst[3] = v.w;
        }
        __syncthreads();
#pragma unroll 8
        for (int dl = 0; dl < 32; dl++) {
            int dg = dc * 32 + dl;
            float w0 = sm->tile[rq][dl];
            float w1 = sm->tile[rq + 64][dl];
            float w2 = sm->tile[rq + 128][dl];
            float w3 = sm->tile[rq + 192][dl];
            u64 p0 = pk2(w0, w0), p1 = pk2(w1, w1), p2 = pk2(w2, w2), p3 = pk2(w3, w3);
#pragma unroll
            for (int k = 0; k < 7; k++) {
                u64 s2 = *(const u64*)&sm->sS[dg][2 * (KLO + k)];
                acc[0][k] = ffma2(s2, p0, acc[0][k]);
                acc[1][k] = ffma2(s2, p1, acc[1][k]);
                acc[2][k] = ffma2(s2, p2, acc[2][k]);
                acc[3][k] = ffma2(s2, p3, acc[3][k]);
            }
        }
    }

    // epilogue: bias + exp-sum over this thread's 7 n-pairs, per r
#pragma unroll
    for (int i = 0; i < 4; i++) {
        int r = rbase + rq + 64 * i;
        int rc = (r <= 999) ? r : 999;
        float cl = cent[2 * rc] * DEG2RADF;
        float co = cent[2 * rc + 1] * DEG2RADF;
        float cc = cosf(cl);
        float den = 0.0f, num = 0.0f;
#pragma unroll
        for (int k = 0; k < 7; k++) {
            float lo, hi; upk2(acc[i][k], lo, hi);
            int n = 2 * (KLO + k);
#pragma unroll
            for (int u = 0; u < 2; u++) {
                int nn = n + u;
                float dotv = u ? hi : lo;
                float dd = hav_km(sm->slat[nn] - cl, sm->slon[nn] - co,
                                  cc * sm->scos[nn]);
                float s = fmaf(dotv, INV_SQRT_D, interp64(sm->Edm, dd * 0.315f));
                s = (sm->sval[nn] != 0.0f) ? s : -1.0e30f;
                float e = __expf(s);        // masked -> exactly 0
                den += e;
                num = fmaf(e, s, num);
            }
        }
        sm->red[h][rq][2 * i] = den;
        sm->red[h][rq][2 * i + 1] = num;
    }
    __syncthreads();

    if (h == 0) {
#pragma unroll
        for (int i = 0; i < 4; i++) {
            float den = 0.0f, num = 0.0f;
#pragma unroll
            for (int hh = 0; hh < 4; hh++) {
                den += sm->red[hh][rq][2 * i];
                num += sm->red[hh][rq][2 * i + 1];
            }
            int r = rbase + rq + 64 * i;
            if (r < RR)
                out[(size_t)b * RR + r] = (den > 0.0f) ? (num / den) : 0.0f;
        }
    }
}

// ---------------- launcher ----------------

extern "C" void kernel_launch(void* const* d_in, const int* in_sizes, int n_in,
                              void* d_out, int out_size) {
    const int*   poi_idx  = (const int*)d_in[0];
    const int*   hour     = (const int*)d_in[1];
    const float* lat      = (const float*)d_in[2];
    const float* lon      = (const float*)d_in[3];
    const float* tmin     = (const float*)d_in[4];
    const float* cent     = (const float*)d_in[5];
    const float* poi_emb  = (const float*)d_in[6];
    const float* time_emb = (const float*)d_in[7];
    const float* E_t      = (const float*)d_in[8];
    const float* E_d      = (const float*)d_in[9];
    const float* E_dm     = (const float*)d_in[10];
    const float* Remb     = (const float*)d_in[11];
    const float* Wq       = (const float*)d_in[12];
    const float* Wk       = (const float*)d_in[13];
    const float* Wv       = (const float*)d_in[14];
    float* out = (float*)d_out;

    cudaFuncSetAttribute(stan_k1, cudaFuncAttributeMaxDynamicSharedMemorySize,
                         (int)sizeof(S1));
    cudaFuncSetAttribute(stan_k2, cudaFuncAttributeMaxDynamicSharedMemorySize,
                         (int)sizeof(S2));

    stan_k0<<<128, 128>>>(Wq, Wk);
    stan_k1<<<BB, 256, sizeof(S1)>>>(poi_idx, hour, lat, lon, tmin,
                                     poi_emb, time_emb, E_t, E_d, Wv);
    stan_k2<<<dim3(4, BB), 256, sizeof(S2)>>>(poi_idx, lat, lon, cent, E_dm, Remb, out);
}

// round 11
// speedup vs baseline: 1.1436x; 1.1436x over previous
#include <cuda_runtime.h>
#include <cuda_bf16.h>
#include <math.h>
#include <cstdint>

// Input order:
// 0 poi_idx(i32 B*N) 1 hour_of_week(i32 B*N) 2 lat 3 lon 4 t_min (f32 B*N)
// 5 region_centroids(R*2) 6 poi_emb((N_POIS+1)*D) 7 time_emb(169*D)
// 8 E_t(64) 9 E_d(64) 10 E_d_match(64) 11 region_emb(R*D) 12 Wq 13 Wk 14 Wv (D*D)
// output: f32 (B, R) = (1024, 1000)

#define BB 1024
#define NN 50
#define RR 1000
#define DD 128
#define DEG2RADF 0.017453292519943295f
#define INV_SQRT_D 0.08838834764831845f   // 1/sqrt(128)

typedef unsigned long long u64;

// scratch
__device__ uint32_t g_Sb[BB * NN * 64];   // S bf16x2, [b][n][d/2]
__device__ uint32_t g_Rb[RR * 64];        // Remb bf16x2, [r][d/2]
__device__ float    g_M[DD * DD];         // M[b][a] = sum_j Wq[j][a]*Wk[j][b]

__device__ __forceinline__ u64 pk2(float lo, float hi) {
    u64 r; asm("mov.b64 %0, {%1, %2};" : "=l"(r) : "f"(lo), "f"(hi)); return r;
}
__device__ __forceinline__ void upk2(u64 v, float& lo, float& hi) {
    asm("mov.b64 {%0, %1}, %2;" : "=f"(lo), "=f"(hi) : "l"(v));
}
__device__ __forceinline__ u64 ffma2(u64 a, u64 b, u64 c) {
    u64 d; asm("fma.rn.f32x2 %0, %1, %2, %3;" : "=l"(d) : "l"(a), "l"(b), "l"(c)); return d;
}
__device__ __forceinline__ uint32_t f2bf2(float2 v) {
    uint32_t r;
    asm("cvt.rn.bf16x2.f32 %0, %1, %2;" : "=r"(r) : "f"(v.y), "f"(v.x));
    return r;
}
__device__ __forceinline__ uint32_t smem_u32(const void* p) {
    uint32_t a;
    asm("{ .reg .u64 t; cvta.to.shared.u64 t, %1; cvt.u32.u64 %0, t; }" : "=r"(a) : "l"(p));
    return a;
}

__device__ __forceinline__ float interp64(const float* t, float x) {
    x = fminf(fmaxf(x, 0.0f), 62.999996f);
    int k = (int)x;
    float f = x - (float)k;
    return t[k] + f * (t[k + 1] - t[k]);
}

// sin(x) for |x| < 0.01 rad: x - x^3/6
__device__ __forceinline__ float sinp(float x) {
    float x2 = x * x;
    return x * fmaf(x2, -0.16666667f, 1.0f);
}

// haversine, asin series (all distances used clipped to <=200km)
__device__ __forceinline__ float hav_km(float dlatr, float dlonr, float cc) {
    float s1 = sinp(0.5f * dlatr);
    float s2 = sinp(0.5f * dlonr);
    float a = fmaf(s1, s1, cc * s2 * s2);
    a = fminf(a, 1.0f);
    float w = sqrtf(a);
    return w * fmaf(2123.6667f, a, 12742.0f);
}

// ---------------- warp MMA helpers (legacy mma.sync, plain sm_103) --------

__device__ __forceinline__ void ldsm_x4(uint32_t addr, uint32_t& r0, uint32_t& r1,
                                        uint32_t& r2, uint32_t& r3) {
    asm volatile("ldmatrix.sync.aligned.m8n8.x4.shared.b16 {%0,%1,%2,%3}, [%4];"
                 : "=r"(r0), "=r"(r1), "=r"(r2), "=r"(r3) : "r"(addr));
}
__device__ __forceinline__ void ldsm_x2(uint32_t addr, uint32_t& r0, uint32_t& r1) {
    asm volatile("ldmatrix.sync.aligned.m8n8.x2.shared.b16 {%0,%1}, [%2];"
                 : "=r"(r0), "=r"(r1) : "r"(addr));
}
__device__ __forceinline__ void mma16816(float* d, uint32_t a0, uint32_t a1,
                                         uint32_t a2, uint32_t a3,
                                         uint32_t b0, uint32_t b1) {
    asm volatile(
        "mma.sync.aligned.m16n8k16.row.col.f32.bf16.bf16.f32 "
        "{%0,%1,%2,%3}, {%4,%5,%6,%7}, {%8,%9}, {%0,%1,%2,%3};"
        : "+f"(d[0]), "+f"(d[1]), "+f"(d[2]), "+f"(d[3])
        : "r"(a0), "r"(a1), "r"(a2), "r"(a3), "r"(b0), "r"(b1));
}

// ---------------- Kernel 0: M = Wq^T Wk;  k0b: Remb -> bf16 ---------------

__global__ void stan_k0(const float* __restrict__ Wq, const float* __restrict__ Wk) {
    int bcol = blockIdx.x;    // 0..127
    int a = threadIdx.x;      // 0..127
    float s0 = 0.f, s1 = 0.f, s2 = 0.f, s3 = 0.f;
#pragma unroll
    for (int j = 0; j < 128; j += 4) {
        s0 = fmaf(__ldg(&Wq[(j + 0) * 128 + a]), __ldg(&Wk[(j + 0) * 128 + bcol]), s0);
        s1 = fmaf(__ldg(&Wq[(j + 1) * 128 + a]), __ldg(&Wk[(j + 1) * 128 + bcol]), s1);
        s2 = fmaf(__ldg(&Wq[(j + 2) * 128 + a]), __ldg(&Wk[(j + 2) * 128 + bcol]), s2);
        s3 = fmaf(__ldg(&Wq[(j + 3) * 128 + a]), __ldg(&Wk[(j + 3) * 128 + bcol]), s3);
    }
    g_M[bcol * 128 + a] = (s0 + s1) + (s2 + s3);
}

__global__ void stan_k0b(const float* __restrict__ Remb) {
    int i = blockIdx.x * 256 + threadIdx.x;    // 64000 bf16x2 words
    if (i < RR * 64) {
        float2 v = ((const float2*)Remb)[i];
        g_Rb[i] = f2bf2(v);
    }
}

// ---------------- Kernel 1: x, Y=xM^T, scores, V, softmax, S (bf16 out) ---

struct S1 {
    float xT[128][52];   // x transposed [d][n]
    float YT[128][52];   // y transposed [j][n]; reused as Vt after scores
    float P[50][52];     // scores -> attn [n][m]
    float Et[64];
    float Ed[64];
    float tmin_s[50];
    float latr[50];
    float lonr[50];
    float coslat[50];
    float validf[50];
    int   psafe[50];
    int   hsafe[50];
};

__device__ __forceinline__ void gemm_pass(const float (*xT)[52], float (*OT)[52],
                                          const float* __restrict__ W,
                                          int j0, int n0, int cnt) {
    u64 a0[7], a1[7];
#pragma unroll
    for (int k = 0; k < 7; k++) { a0[k] = 0ull; a1[k] = 0ull; }
    const float4* w0 = (const float4*)(W + j0 * 128);
    const float4* w1 = (const float4*)(W + (j0 + 1) * 128);
#pragma unroll 4
    for (int d4 = 0; d4 < 32; d4++) {
        float4 wa = __ldg(&w0[d4]);
        float4 wb = __ldg(&w1[d4]);
        float wav[4] = {wa.x, wa.y, wa.z, wa.w};
        float wbv[4] = {wb.x, wb.y, wb.z, wb.w};
#pragma unroll
        for (int dd = 0; dd < 4; dd++) {
            int d = 4 * d4 + dd;
            u64 p0 = pk2(wav[dd], wav[dd]);
            u64 p1 = pk2(wbv[dd], wbv[dd]);
#pragma unroll
            for (int k = 0; k < 7; k++) {
                u64 x2 = *(const u64*)&xT[d][n0 + 2 * k];
                a0[k] = ffma2(x2, p0, a0[k]);
                a1[k] = ffma2(x2, p1, a1[k]);
            }
        }
    }
#pragma unroll
    for (int k = 0; k < 7; k++) {
        if (k < cnt) {
            *(u64*)&OT[j0][n0 + 2 * k]     = a0[k];
            *(u64*)&OT[j0 + 1][n0 + 2 * k] = a1[k];
        }
    }
}

__global__ void __launch_bounds__(256, 3)
stan_k1(const int* __restrict__ poi_idx, const int* __restrict__ hour,
        const float* __restrict__ lat, const float* __restrict__ lon,
        const float* __restrict__ tmin,
        const float* __restrict__ poi_emb, const float* __restrict__ time_emb,
        const float* __restrict__ E_t, const float* __restrict__ E_d,
        const float* __restrict__ Wv) {
    extern __shared__ char smraw[];
    S1* sm = (S1*)smraw;
    const int b = blockIdx.x;
    const int t = threadIdx.x;

    if (t < 50) {
        int pi = poi_idx[b * 50 + t];
        bool pad = pi < 0;
        sm->psafe[t] = pad ? 50000 : pi;
        sm->hsafe[t] = pad ? 0 : hour[b * 50 + t];
        sm->validf[t] = pad ? 0.0f : 1.0f;
        float la = lat[b * 50 + t] * DEG2RADF;
        float lo = lon[b * 50 + t] * DEG2RADF;
        sm->latr[t] = la; sm->lonr[t] = lo;
        sm->coslat[t] = cosf(la);
        sm->tmin_s[t] = tmin[b * 50 + t];
    }
    if (t >= 64 && t < 128) { sm->Et[t - 64] = E_t[t - 64]; sm->Ed[t - 64] = E_d[t - 64]; }
    __syncthreads();

    for (int idx = t; idx < 50 * 128; idx += 256) {
        int n = idx >> 7, d = idx & 127;
        sm->xT[d][n] = poi_emb[sm->psafe[n] * 128 + d] + time_emb[sm->hsafe[n] * 128 + d];
    }
    __syncthreads();

    const int jp = t & 63;
    const int qtr = t >> 6;
    const int j0 = 2 * jp;
    const int n0tab[4] = {0, 14, 26, 38};
    const int cnttab[4] = {7, 6, 6, 6};
    const int n0 = n0tab[qtr];
    const int cnt = cnttab[qtr];

    // Y = x M^T   (scores = Y x^T)
    gemm_pass(sm->xT, sm->YT, g_M, j0, n0, cnt);
    __syncthreads();

    // scores
    for (int q = t; q < 1250; q += 256) {
        int np = q / 50, m = q - np * 50;
        int n = 2 * np;
        u64 acc = 0ull;
#pragma unroll 16
        for (int d = 0; d < 128; d++) {
            float xv = sm->xT[d][m];
            acc = ffma2(*(const u64*)&sm->YT[d][n], pk2(xv, xv), acc);
        }
        float lo, hi; upk2(acc, lo, hi);
        float vm = sm->validf[m];
        float ltm = sm->latr[m], lnm = sm->lonr[m], clm = sm->coslat[m], tm = sm->tmin_s[m];
#pragma unroll
        for (int u = 0; u < 2; u++) {
            int nn = n + u;
            float dotv = u ? hi : lo;
            float vp = sm->validf[nn] * vm;
            float dtm = fabsf(sm->tmin_s[nn] - tm) * vp;
            float dd = hav_km(ltm - sm->latr[nn], lnm - sm->lonr[nn],
                              sm->coslat[nn] * clm) * vp;
            float s = dotv * INV_SQRT_D
                    + interp64(sm->Et, fminf(dtm, 10080.0f) * 0.00625f)
                    + interp64(sm->Ed, fminf(dd, 200.0f) * 0.315f);
            sm->P[nn][m] = (vm != 0.0f) ? s : -1.0e30f;
        }
    }
    __syncthreads();

    // V pass (overwrites YT as Vt[j][m-pairs])
    gemm_pass(sm->xT, sm->YT, Wv, j0, n0, cnt);

    // row softmax
    if (t < 50) {
        float mx = -3.0e38f;
#pragma unroll
        for (int m = 0; m < 50; m++) mx = fmaxf(mx, sm->P[t][m]);
        if (mx <= -9.0e29f) {
            for (int m = 0; m < 50; m++) sm->P[t][m] = 0.0f;
        } else {
            float sum = 0.0f;
#pragma unroll
            for (int m = 0; m < 50; m++) {
                float e = __expf(sm->P[t][m] - mx);
                sm->P[t][m] = e; sum += e;
            }
            float inv = 1.0f / sum;
#pragma unroll
            for (int m = 0; m < 50; m++) sm->P[t][m] *= inv;
        }
    }
    __syncthreads();

    // S = attn @ V  -> bf16x2 global
    float (*Vt)[52] = sm->YT;
    const int nrows = 2 * cnt;
    for (int nn = 0; nn < nrows; nn++) {
        int n = n0 + nn;
        u64 acc0 = 0ull, acc1 = 0ull;
#pragma unroll
        for (int i = 0; i < 25; i++) {
            u64 a2 = *(const u64*)&sm->P[n][2 * i];
            acc0 = ffma2(a2, *(const u64*)&Vt[j0][2 * i], acc0);
            acc1 = ffma2(a2, *(const u64*)&Vt[j0 + 1][2 * i], acc1);
        }
        float l0, h0, l1, h1; upk2(acc0, l0, h0); upk2(acc1, l1, h1);
        g_Sb[((size_t)b * 50 + n) * 64 + jp] = f2bf2(make_float2(l0 + h0, l1 + h1));
    }
}

// ---------------- Kernel 2: mma.sync bf16 GEMM + quad-reduce softmax ------
// Per block: A = Remb chunk [M=128 x K=128] bf16, B = S for 2 batches packed
// at n-rows 0-49 (b0) and 64-113 (b1) [N=128 x K=128] bf16 (pad rows zero).
// Both K-contiguous, pitch 272B (17x16B -> conflict-free ldmatrix).
// Warp w owns M rows 16w..16w+15, all N. D row = region, col = n:
// softmax over n = per-thread partial + 2-round quad butterfly.

#define K2_A   0
#define K2_B   34816
#define K2_SC  69632
#define K2_SMEM (K2_SC + 576 * 4)

__global__ void __launch_bounds__(256, 2)
stan_k2m(const int* __restrict__ poi_idx, const float* __restrict__ lat,
         const float* __restrict__ lon, const float* __restrict__ cent,
         const float* __restrict__ E_dm, float* __restrict__ out) {
    extern __shared__ char smr[];
    uint32_t sb = smem_u32(smr);
    float* SC   = (float*)(smr + K2_SC);
    float* slat = SC;          // [2][64] indexed by col c = 64h+nn
    float* slon = SC + 128;
    float* scos = SC + 256;
    float* sval = SC + 384;
    float* Edm  = SC + 512;    // 64
    const int bp = blockIdx.y;           // batch pair
    const int rbase = blockIdx.x * 128;
    const int t = threadIdx.x;
    const int w = t >> 5, lane = t & 31;

    if (t < 128) {
        int h = t >> 6, n = t & 63;
        int b = 2 * bp + h;
        if (n < 50) {
            sval[t] = (poi_idx[b * 50 + n] < 0) ? 0.0f : 1.0f;
            float la = lat[b * 50 + n] * DEG2RADF;
            float lo = lon[b * 50 + n] * DEG2RADF;
            slat[t] = la; slon[t] = lo; scos[t] = cosf(la);
        } else { sval[t] = 0.0f; slat[t] = 0.0f; slon[t] = 0.0f; scos[t] = 1.0f; }
    } else if (t < 192) {
        Edm[t - 128] = E_dm[t - 128];
    }

    // A tile (clamp r>999 to 999; store guarded later)
    for (int p = t; p < 8192; p += 256) {
        int row = p >> 6, pi = p & 63;
        int r = rbase + row; if (r > 999) r = 999;
        *(uint32_t*)(smr + K2_A + row * 272 + pi * 4) = g_Rb[r * 64 + pi];
    }
    // B tile (rows 50-63 / 114-127 zero)
    for (int p = t; p < 8192; p += 256) {
        int row = p >> 6, pi = p & 63;
        int h = row >> 6, nn = row & 63;
        uint32_t v = (nn < 50) ? g_Sb[((size_t)(2 * bp + h) * 50 + nn) * 64 + pi] : 0u;
        *(uint32_t*)(smr + K2_B + row * 272 + pi * 4) = v;
    }
    __syncthreads();

    const uint32_t aaddr = sb + K2_A + (16 * w + (lane & 15)) * 272 + ((lane >> 4) << 4);
    const uint32_t baddr = sb + K2_B + (lane & 7) * 272 + (((lane >> 3) & 1) << 4);

    float d[16][4];
#pragma unroll
    for (int nt = 0; nt < 16; nt++)
#pragma unroll
        for (int u = 0; u < 4; u++) d[nt][u] = 0.0f;

#pragma unroll
    for (int ks = 0; ks < 8; ks++) {
        uint32_t a0, a1, a2, a3;
        ldsm_x4(aaddr + ks * 32, a0, a1, a2, a3);
#pragma unroll
        for (int nt = 0; nt < 16; nt++) {
            uint32_t b0, b1;
            ldsm_x2(baddr + nt * 2176 + ks * 32, b0, b1);
            mma16816(d[nt], a0, a1, a2, a3, b0, b1);
        }
    }

    // epilogue: bias + exp; quad-lane butterfly reduce over n
    const int g = lane >> 2, qp = lane & 3;
#pragma unroll
    for (int rs = 0; rs < 2; rs++) {
        int r = rbase + 16 * w + g + 8 * rs;
        int rc = (r > 999) ? 999 : r;
        float cl = cent[2 * rc] * DEG2RADF;
        float co = cent[2 * rc + 1] * DEG2RADF;
        float cc = cosf(cl);
        float den0 = 0.f, num0 = 0.f, den1 = 0.f, num1 = 0.f;
#pragma unroll
        for (int nt = 0; nt < 16; nt++) {
#pragma unroll
            for (int u = 0; u < 2; u++) {
                int c = 8 * nt + 2 * qp + u;
                float v = d[nt][2 * rs + u];
                float dd = hav_km(slat[c] - cl, slon[c] - co, cc * scos[c]);
                float s = fmaf(v, INV_SQRT_D, interp64(Edm, dd * 0.315f));
                float e = sval[c] * __expf(s);    // masked -> exactly 0
                if (nt < 8) { den0 += e; num0 = fmaf(e, s, num0); }
                else        { den1 += e; num1 = fmaf(e, s, num1); }
            }
        }
#pragma unroll
        for (int off = 1; off <= 2; off <<= 1) {
            den0 += __shfl_xor_sync(0xffffffffu, den0, off);
            num0 += __shfl_xor_sync(0xffffffffu, num0, off);
            den1 += __shfl_xor_sync(0xffffffffu, den1, off);
            num1 += __shfl_xor_sync(0xffffffffu, num1, off);
        }
        if (qp == 0 && r < RR) {
            out[(size_t)(2 * bp + 0) * RR + r] = (den0 > 0.f) ? (num0 / den0) : 0.f;
            out[(size_t)(2 * bp + 1) * RR + r] = (den1 > 0.f) ? (num1 / den1) : 0.f;
        }
    }
}

// ---------------- launcher ----------------

extern "C" void kernel_launch(void* const* d_in, const int* in_sizes, int n_in,
                              void* d_out, int out_size) {
    const int*   poi_idx  = (const int*)d_in[0];
    const int*   hour     = (const int*)d_in[1];
    const float* lat      = (const float*)d_in[2];
    const float* lon      = (const float*)d_in[3];
    const float* tmin     = (const float*)d_in[4];
    const float* cent     = (const float*)d_in[5];
    const float* poi_emb  = (const float*)d_in[6];
    const float* time_emb = (const float*)d_in[7];
    const float* E_t      = (const float*)d_in[8];
    const float* E_d      = (const float*)d_in[9];
    const float* E_dm     = (const float*)d_in[10];
    const float* Remb     = (const float*)d_in[11];
    const float* Wq       = (const float*)d_in[12];
    const float* Wk       = (const float*)d_in[13];
    const float* Wv       = (const float*)d_in[14];
    float* out = (float*)d_out;

    cudaFuncSetAttribute(stan_k1, cudaFuncAttributeMaxDynamicSharedMemorySize,
                         (int)sizeof(S1));
    cudaFuncSetAttribute(stan_k2m, cudaFuncAttributeMaxDynamicSharedMemorySize,
                         K2_SMEM);

    stan_k0<<<128, 128>>>(Wq, Wk);
    stan_k0b<<<250, 256>>>(Remb);
    stan_k1<<<BB, 256, sizeof(S1)>>>(poi_idx, hour, lat, lon, tmin,
                                     poi_emb, time_emb, E_t, E_d, Wv);
    stan_k2m<<<dim3(8, BB / 2), 256, K2_SMEM>>>(poi_idx, lat, lon, cent, E_dm, out);
}

// round 16
// speedup vs baseline: 1.9144x; 1.6740x over previous
#include <cuda_runtime.h>
#include <cuda_bf16.h>
#include <math.h>
#include <cstdint>

// Input order:
// 0 poi_idx(i32 B*N) 1 hour_of_week(i32 B*N) 2 lat 3 lon 4 t_min (f32 B*N)
// 5 region_centroids(R*2) 6 poi_emb((N_POIS+1)*D) 7 time_emb(169*D)
// 8 E_t(64) 9 E_d(64) 10 E_d_match(64) 11 region_emb(R*D) 12 Wq 13 Wk 14 Wv (D*D)
// output: f32 (B, R) = (1024, 1000)

#define BB 1024
#define NN 50
#define RR 1000
#define DD 128
#define DEG2RADF 0.017453292519943295f
#define INV_SQRT_D 0.08838834764831845f   // 1/sqrt(128)

// scratch
__device__ uint32_t g_Sb[BB * NN * 64];   // S bf16x2, [b][n][d/2]
__device__ uint32_t g_Rb[RR * 64];        // Remb bf16x2, [r][d/2]
__device__ uint32_t g_Mb[DD * 64];        // M bf16x2, [bcol][a/2], M[a][b]=sum Wq[t][a]Wk[t][b]
__device__ uint32_t g_Wvb[DD * 64];       // Wv bf16x2, [d][a/2]

__device__ __forceinline__ uint32_t f2bf2(float2 v) {
    uint32_t r;
    asm("cvt.rn.bf16x2.f32 %0, %1, %2;" : "=r"(r) : "f"(v.y), "f"(v.x));
    return r;
}
__device__ __forceinline__ uint32_t smem_u32(const void* p) {
    uint32_t a;
    asm("{ .reg .u64 t; cvta.to.shared.u64 t, %1; cvt.u32.u64 %0, t; }" : "=r"(a) : "l"(p));
    return a;
}

__device__ __forceinline__ float interp64(const float* t, float x) {
    x = fminf(fmaxf(x, 0.0f), 62.999996f);
    int k = (int)x;
    float f = x - (float)k;
    return t[k] + f * (t[k + 1] - t[k]);
}

// sin(x) for |x| < 0.01 rad: x - x^3/6
__device__ __forceinline__ float sinp(float x) {
    float x2 = x * x;
    return x * fmaf(x2, -0.16666667f, 1.0f);
}

// haversine, asin series (all distances used clipped to <=200km)
__device__ __forceinline__ float hav_km(float dlatr, float dlonr, float cc) {
    float s1 = sinp(0.5f * dlatr);
    float s2 = sinp(0.5f * dlonr);
    float a = fmaf(s1, s1, cc * s2 * s2);
    a = fminf(a, 1.0f);
    float w = sqrtf(a);
    return w * fmaf(2123.6667f, a, 12742.0f);
}

// ---------------- warp MMA helpers (legacy mma.sync, plain sm_103) --------

__device__ __forceinline__ void ldsm_x4(uint32_t addr, uint32_t& r0, uint32_t& r1,
                                        uint32_t& r2, uint32_t& r3) {
    asm volatile("ldmatrix.sync.aligned.m8n8.x4.shared.b16 {%0,%1,%2,%3}, [%4];"
                 : "=r"(r0), "=r"(r1), "=r"(r2), "=r"(r3) : "r"(addr));
}
__device__ __forceinline__ void ldsm_x2(uint32_t addr, uint32_t& r0, uint32_t& r1) {
    asm volatile("ldmatrix.sync.aligned.m8n8.x2.shared.b16 {%0,%1}, [%2];"
                 : "=r"(r0), "=r"(r1) : "r"(addr));
}
__device__ __forceinline__ void ldsm_x2t(uint32_t addr, uint32_t& r0, uint32_t& r1) {
    asm volatile("ldmatrix.sync.aligned.m8n8.x2.trans.shared.b16 {%0,%1}, [%2];"
                 : "=r"(r0), "=r"(r1) : "r"(addr));
}
__device__ __forceinline__ void mma16816(float* d, uint32_t a0, uint32_t a1,
                                         uint32_t a2, uint32_t a3,
                                         uint32_t b0, uint32_t b1) {
    asm volatile(
        "mma.sync.aligned.m16n8k16.row.col.f32.bf16.bf16.f32 "
        "{%0,%1,%2,%3}, {%4,%5,%6,%7}, {%8,%9}, {%0,%1,%2,%3};"
        : "+f"(d[0]), "+f"(d[1]), "+f"(d[2]), "+f"(d[3])
        : "r"(a0), "r"(a1), "r"(a2), "r"(a3), "r"(b0), "r"(b1));
}

// ---------------- Kernel 0 family: precompute bf16 operands --------------

// M = Wq^T Wk, stored bf16 as [bcol][a] pairs
__global__ void stan_k0(const float* __restrict__ Wq, const float* __restrict__ Wk) {
    __shared__ float col[128];
    int bcol = blockIdx.x;    // 0..127
    int a = threadIdx.x;      // 0..127
    float s0 = 0.f, s1 = 0.f, s2 = 0.f, s3 = 0.f;
#pragma unroll
    for (int j = 0; j < 128; j += 4) {
        s0 = fmaf(__ldg(&Wq[(j + 0) * 128 + a]), __ldg(&Wk[(j + 0) * 128 + bcol]), s0);
        s1 = fmaf(__ldg(&Wq[(j + 1) * 128 + a]), __ldg(&Wk[(j + 1) * 128 + bcol]), s1);
        s2 = fmaf(__ldg(&Wq[(j + 2) * 128 + a]), __ldg(&Wk[(j + 2) * 128 + bcol]), s2);
        s3 = fmaf(__ldg(&Wq[(j + 3) * 128 + a]), __ldg(&Wk[(j + 3) * 128 + bcol]), s3);
    }
    col[a] = (s0 + s1) + (s2 + s3);
    __syncthreads();
    if (a < 64)
        g_Mb[bcol * 64 + a] = f2bf2(make_float2(col[2 * a], col[2 * a + 1]));
}

__global__ void stan_k0b(const float* __restrict__ Remb) {
    int i = blockIdx.x * 256 + threadIdx.x;    // 64000 bf16x2 words
    if (i < RR * 64) {
        float2 v = ((const float2*)Remb)[i];
        g_Rb[i] = f2bf2(v);
    }
}

__global__ void stan_k0c(const float* __restrict__ Wv) {
    int i = blockIdx.x * 256 + threadIdx.x;    // 8192 words
    if (i < DD * 64) {
        float2 v = ((const float2*)Wv)[i];
        g_Wvb[i] = f2bf2(v);
    }
}

// ---------------- Kernel 1: tensor-core attention per batch ---------------
// smem (bytes): XB x bf16 [64][pitch 272] | WB weights bf16 [128][272]
// YB Y bf16 (later V bf16) [64][272] | PF scores f32 [64][pitch 68 f]
// PB attn bf16 [64][pitch 144B] | SC scalars

#define XB_O 0
#define WB_O 17408
#define YB_O 52224
#define PF_O 69632
#define PB_O 87040
#define SC_O 96256
#define K1_SMEM (SC_O + 2304)

__global__ void __launch_bounds__(256, 2)
stan_k1(const int* __restrict__ poi_idx, const int* __restrict__ hour,
        const float* __restrict__ lat, const float* __restrict__ lon,
        const float* __restrict__ tmin,
        const float* __restrict__ poi_emb, const float* __restrict__ time_emb,
        const float* __restrict__ E_t, const float* __restrict__ E_d) {
    extern __shared__ char smr[];
    uint32_t sb = smem_u32(smr);
    float* PF   = (float*)(smr + PF_O);
    float* SC   = (float*)(smr + SC_O);
    float* Et     = SC;          // 64
    float* Ed     = SC + 64;     // 64
    float* tmin_s = SC + 128;    // 64
    float* latr   = SC + 192;
    float* lonr   = SC + 256;
    float* coslat = SC + 320;
    float* validf = SC + 384;
    int*   psafe  = (int*)(SC + 448);
    int*   hsafe  = (int*)(SC + 512);

    const int b = blockIdx.x;
    const int t = threadIdx.x;
    const int w = t >> 5, lane = t & 31;
    const int mrow = 16 * (w & 3);
    const int nh = w >> 2;
    const int g = lane >> 2, qp = lane & 3;

    if (t < 64) {
        if (t < 50) {
            int pi = poi_idx[b * 50 + t];
            bool pad = pi < 0;
            psafe[t] = pad ? 50000 : pi;
            hsafe[t] = pad ? 0 : hour[b * 50 + t];
            validf[t] = pad ? 0.0f : 1.0f;
            float la = lat[b * 50 + t] * DEG2RADF;
            float lo = lon[b * 50 + t] * DEG2RADF;
            latr[t] = la; lonr[t] = lo;
            coslat[t] = cosf(la);
            tmin_s[t] = tmin[b * 50 + t];
        } else {
            psafe[t] = 50000; hsafe[t] = 0; validf[t] = 0.0f;
            latr[t] = 0.0f; lonr[t] = 0.0f; coslat[t] = 1.0f; tmin_s[t] = 0.0f;
        }
    }
    if (t >= 64 && t < 128) { Et[t - 64] = E_t[t - 64]; Ed[t - 64] = E_d[t - 64]; }
    // load M bf16 -> WB
    for (int i = t; i < 128 * 64; i += 256) {
        int row = i >> 6, cw = i & 63;
        *(uint32_t*)(smr + WB_O + row * 272 + cw * 4) = g_Mb[i];
    }
    __syncthreads();

    // gather x -> bf16 XB; zero rows 50-63
    for (int i = t; i < 50 * 64; i += 256) {
        int n = i >> 6, dw = i & 63;
        float2 p = *(const float2*)(poi_emb + (size_t)psafe[n] * 128 + 2 * dw);
        float2 q = *(const float2*)(time_emb + (size_t)hsafe[n] * 128 + 2 * dw);
        *(uint32_t*)(smr + XB_O + n * 272 + dw * 4) =
            f2bf2(make_float2(p.x + q.x, p.y + q.y));
    }
    for (int i = t; i < 14 * 64; i += 256) {
        int n = 50 + (i >> 6), dw = i & 63;
        *(uint32_t*)(smr + XB_O + n * 272 + dw * 4) = 0u;
    }
    __syncthreads();

    // ---- MMA1: Y = x M^T  [64 x 128] ----
    {
        float d1[8][4];
#pragma unroll
        for (int nt = 0; nt < 8; nt++)
#pragma unroll
            for (int u = 0; u < 4; u++) d1[nt][u] = 0.0f;
        uint32_t aa = sb + XB_O + (mrow + (lane & 15)) * 272 + ((lane >> 4) << 4);
        uint32_t ba = sb + WB_O + ((nh << 6) + (lane & 7)) * 272 + (((lane >> 3) & 1) << 4);
#pragma unroll
        for (int ks = 0; ks < 8; ks++) {
            uint32_t a0, a1, a2, a3;
            ldsm_x4(aa + ks * 32, a0, a1, a2, a3);
#pragma unroll
            for (int nt = 0; nt < 8; nt++) {
                uint32_t b0, b1;
                ldsm_x2(ba + nt * 2176 + ks * 32, b0, b1);
                mma16816(d1[nt], a0, a1, a2, a3, b0, b1);
            }
        }
#pragma unroll
        for (int nt = 0; nt < 8; nt++)
#pragma unroll
            for (int rs = 0; rs < 2; rs++) {
                int row = mrow + g + 8 * rs;
                int word = (nh << 5) + 4 * nt + qp;
                *(uint32_t*)(smr + YB_O + row * 272 + word * 4) =
                    f2bf2(make_float2(d1[nt][2 * rs], d1[nt][2 * rs + 1]));
            }
    }
    __syncthreads();

    // ---- MMA2: scores = Y x^T  [64 x 64] -> PF f32 ----
    {
        float d2[4][4];
#pragma unroll
        for (int nt = 0; nt < 4; nt++)
#pragma unroll
            for (int u = 0; u < 4; u++) d2[nt][u] = 0.0f;
        uint32_t aa = sb + YB_O + (mrow + (lane & 15)) * 272 + ((lane >> 4) << 4);
        uint32_t ba = sb + XB_O + ((nh << 5) + (lane & 7)) * 272 + (((lane >> 3) & 1) << 4);
#pragma unroll
        for (int ks = 0; ks < 8; ks++) {
            uint32_t a0, a1, a2, a3;
            ldsm_x4(aa + ks * 32, a0, a1, a2, a3);
#pragma unroll
            for (int nt = 0; nt < 4; nt++) {
                uint32_t b0, b1;
                ldsm_x2(ba + nt * 2176 + ks * 32, b0, b1);
                mma16816(d2[nt], a0, a1, a2, a3, b0, b1);
            }
        }
#pragma unroll
        for (int nt = 0; nt < 4; nt++)
#pragma unroll
            for (int rs = 0; rs < 2; rs++) {
                int row = mrow + g + 8 * rs;
                int col = (nh << 5) + 8 * nt + 2 * qp;
                *(float2*)(PF + row * 68 + col) =
                    make_float2(d2[nt][2 * rs], d2[nt][2 * rs + 1]);
            }
    }
    // load Wv bf16 -> WB (M no longer needed)
    for (int i = t; i < 128 * 64; i += 256) {
        int row = i >> 6, cw = i & 63;
        *(uint32_t*)(smr + WB_O + row * 272 + cw * 4) = g_Wvb[i];
    }
    __syncthreads();

    // ---- bias + mask epilogue on PF ----
    for (int q = t; q < 2500; q += 256) {
        int n = q / 50, m = q - n * 50;
        float dotv = PF[n * 68 + m];
        float vm = validf[m];
        float vp = validf[n] * vm;
        float dtm = fabsf(tmin_s[n] - tmin_s[m]) * vp;
        float dd = hav_km(latr[m] - latr[n], lonr[m] - lonr[n],
                          coslat[n] * coslat[m]) * vp;
        float s = dotv * INV_SQRT_D
                + interp64(Et, fminf(dtm, 10080.0f) * 0.00625f)
                + interp64(Ed, fminf(dd, 200.0f) * 0.315f);
        PF[n * 68 + m] = (vm != 0.0f) ? s : -1.0e30f;
    }
    __syncthreads();

    // ---- row softmax ----
    if (t < 50) {
        float mx = -3.0e38f;
#pragma unroll
        for (int m = 0; m < 50; m++) mx = fmaxf(mx, PF[t * 68 + m]);
        if (mx <= -9.0e29f) {
            for (int m = 0; m < 50; m++) PF[t * 68 + m] = 0.0f;
        } else {
            float sum = 0.0f;
#pragma unroll
            for (int m = 0; m < 50; m++) {
                float e = __expf(PF[t * 68 + m] - mx);
                PF[t * 68 + m] = e; sum += e;
            }
            float inv = 1.0f / sum;
#pragma unroll
            for (int m = 0; m < 50; m++) PF[t * 68 + m] *= inv;
        }
    }
    __syncthreads();

    // ---- MMA3: V = x Wv^T [64 x 128] -> VB (overlay YB) bf16 ----
    {
        float d3[8][4];
#pragma unroll
        for (int nt = 0; nt < 8; nt++)
#pragma unroll
            for (int u = 0; u < 4; u++) d3[nt][u] = 0.0f;
        uint32_t aa = sb + XB_O + (mrow + (lane & 15)) * 272 + ((lane >> 4) << 4);
        uint32_t ba = sb + WB_O + ((nh << 6) + (lane & 7)) * 272 + (((lane >> 3) & 1) << 4);
#pragma unroll
        for (int ks = 0; ks < 8; ks++) {
            uint32_t a0, a1, a2, a3;
            ldsm_x4(aa + ks * 32, a0, a1, a2, a3);
#pragma unroll
            for (int nt = 0; nt < 8; nt++) {
                uint32_t b0, b1;
                ldsm_x2(ba + nt * 2176 + ks * 32, b0, b1);
                mma16816(d3[nt], a0, a1, a2, a3, b0, b1);
            }
        }
        __syncthreads();   // YB reads (none now) / ensure all prior YB use done
#pragma unroll
        for (int nt = 0; nt < 8; nt++)
#pragma unroll
            for (int rs = 0; rs < 2; rs++) {
                int row = mrow + g + 8 * rs;          // m
                int word = (nh << 5) + 4 * nt + qp;   // d/2
                *(uint32_t*)(smr + YB_O + row * 272 + word * 4) =
                    f2bf2(make_float2(d3[nt][2 * rs], d3[nt][2 * rs + 1]));
            }
    }
    // convert attn PF -> PB bf16 [n][m] pitch 144B
    for (int i = t; i < 64 * 32; i += 256) {
        int row = i >> 5, cw = i & 31;
        float2 v = *(float2*)(PF + row * 68 + 2 * cw);
        *(uint32_t*)(smr + PB_O + row * 144 + cw * 4) = f2bf2(v);
    }
    __syncthreads();

    // ---- MMA4: S = attn @ V  [64 x 128], B via ldmatrix.trans on V[m][d] ----
    {
        float d4[8][4];
#pragma unroll
        for (int nt = 0; nt < 8; nt++)
#pragma unroll
            for (int u = 0; u < 4; u++) d4[nt][u] = 0.0f;
        uint32_t aa = sb + PB_O + (mrow + (lane & 15)) * 144 + ((lane >> 4) << 4);
#pragma unroll
        for (int ks = 0; ks < 4; ks++) {
            uint32_t a0, a1, a2, a3;
            ldsm_x4(aa + ks * 32, a0, a1, a2, a3);
            uint32_t brow = sb + YB_O + (16 * ks + (lane & 15)) * 272;
#pragma unroll
            for (int nt = 0; nt < 8; nt++) {
                uint32_t b0, b1;
                ldsm_x2t(brow + ((nh << 6) + 8 * nt) * 2, b0, b1);
                mma16816(d4[nt], a0, a1, a2, a3, b0, b1);
            }
        }
#pragma unroll
        for (int nt = 0; nt < 8; nt++)
#pragma unroll
            for (int rs = 0; rs < 2; rs++) {
                int n = mrow + g + 8 * rs;
                if (n < 50) {
                    int word = (nh << 5) + 4 * nt + qp;
                    g_Sb[((size_t)b * 50 + n) * 64 + word] =
                        f2bf2(make_float2(d4[nt][2 * rs], d4[nt][2 * rs + 1]));
                }
            }
    }
}

// ---------------- Kernel 2: mma.sync bf16 GEMM + quad-reduce softmax ------

#define K2_A   0
#define K2_B   34816
#define K2_SC  69632
#define K2_SMEM (K2_SC + 576 * 4)

__global__ void __launch_bounds__(256, 2)
stan_k2m(const int* __restrict__ poi_idx, const float* __restrict__ lat,
         const float* __restrict__ lon, const float* __restrict__ cent,
         const float* __restrict__ E_dm, float* __restrict__ out) {
    extern __shared__ char smr[];
    uint32_t sb = smem_u32(smr);
    float* SC   = (float*)(smr + K2_SC);
    float* slat = SC;          // [2][64] indexed by col c = 64h+nn
    float* slon = SC + 128;
    float* scos = SC + 256;
    float* sval = SC + 384;
    float* Edm  = SC + 512;    // 64
    const int bp = blockIdx.y;           // batch pair
    const int rbase = blockIdx.x * 128;
    const int t = threadIdx.x;
    const int w = t >> 5, lane = t & 31;

    if (t < 128) {
        int h = t >> 6, n = t & 63;
        int b = 2 * bp + h;
        if (n < 50) {
            sval[t] = (poi_idx[b * 50 + n] < 0) ? 0.0f : 1.0f;
            float la = lat[b * 50 + n] * DEG2RADF;
            float lo = lon[b * 50 + n] * DEG2RADF;
            slat[t] = la; slon[t] = lo; scos[t] = cosf(la);
        } else { sval[t] = 0.0f; slat[t] = 0.0f; slon[t] = 0.0f; scos[t] = 1.0f; }
    } else if (t < 192) {
        Edm[t - 128] = E_dm[t - 128];
    }

    // A tile (clamp r>999 to 999; store guarded later)
    for (int p = t; p < 8192; p += 256) {
        int row = p >> 6, pi = p & 63;
        int r = rbase + row; if (r > 999) r = 999;
        *(uint32_t*)(smr + K2_A + row * 272 + pi * 4) = g_Rb[r * 64 + pi];
    }
    // B tile (rows 50-63 / 114-127 zero)
    for (int p = t; p < 8192; p += 256) {
        int row = p >> 6, pi = p & 63;
        int h = row >> 6, nn = row & 63;
        uint32_t v = (nn < 50) ? g_Sb[((size_t)(2 * bp + h) * 50 + nn) * 64 + pi] : 0u;
        *(uint32_t*)(smr + K2_B + row * 272 + pi * 4) = v;
    }
    __syncthreads();

    const uint32_t aaddr = sb + K2_A + (16 * w + (lane & 15)) * 272 + ((lane >> 4) << 4);
    const uint32_t baddr = sb + K2_B + (lane & 7) * 272 + (((lane >> 3) & 1) << 4);

    float d[16][4];
#pragma unroll
    for (int nt = 0; nt < 16; nt++)
#pragma unroll
        for (int u = 0; u < 4; u++) d[nt][u] = 0.0f;

#pragma unroll
    for (int ks = 0; ks < 8; ks++) {
        uint32_t a0, a1, a2, a3;
        ldsm_x4(aaddr + ks * 32, a0, a1, a2, a3);
#pragma unroll
        for (int nt = 0; nt < 16; nt++) {
            uint32_t b0, b1;
            ldsm_x2(baddr + nt * 2176 + ks * 32, b0, b1);
            mma16816(d[nt], a0, a1, a2, a3, b0, b1);
        }
    }

    // epilogue: bias + exp; quad-lane butterfly reduce over n
    const int g = lane >> 2, qp = lane & 3;
#pragma unroll
    for (int rs = 0; rs < 2; rs++) {
        int r = rbase + 16 * w + g + 8 * rs;
        int rc = (r > 999) ? 999 : r;
        float cl = cent[2 * rc] * DEG2RADF;
        float co = cent[2 * rc + 1] * DEG2RADF;
        float cc = cosf(cl);
        float den0 = 0.f, num0 = 0.f, den1 = 0.f, num1 = 0.f;
#pragma unroll
        for (int nt = 0; nt < 16; nt++) {
#pragma unroll
            for (int u = 0; u < 2; u++) {
                int c = 8 * nt + 2 * qp + u;
                float v = d[nt][2 * rs + u];
                float dd = hav_km(slat[c] - cl, slon[c] - co, cc * scos[c]);
                float s = fmaf(v, INV_SQRT_D, interp64(Edm, dd * 0.315f));
                float e = sval[c] * __expf(s);    // masked -> exactly 0
                if (nt < 8) { den0 += e; num0 = fmaf(e, s, num0); }
                else        { den1 += e; num1 = fmaf(e, s, num1); }
            }
        }
#pragma unroll
        for (int off = 1; off <= 2; off <<= 1) {
            den0 += __shfl_xor_sync(0xffffffffu, den0, off);
            num0 += __shfl_xor_sync(0xffffffffu, num0, off);
            den1 += __shfl_xor_sync(0xffffffffu, den1, off);
            num1 += __shfl_xor_sync(0xffffffffu, num1, off);
        }
        if (qp == 0 && r < RR) {
            out[(size_t)(2 * bp + 0) * RR + r] = (den0 > 0.f) ? (num0 / den0) : 0.f;
            out[(size_t)(2 * bp + 1) * RR + r] = (den1 > 0.f) ? (num1 / den1) : 0.f;
        }
    }
}

// ---------------- launcher ----------------

extern "C" void kernel_launch(void* const* d_in, const int* in_sizes, int n_in,
                              void* d_out, int out_size) {
    const int*   poi_idx  = (const int*)d_in[0];
    const int*   hour     = (const int*)d_in[1];
    const float* lat      = (const float*)d_in[2];
    const float* lon      = (const float*)d_in[3];
    const float* tmin     = (const float*)d_in[4];
    const float* cent     = (const float*)d_in[5];
    const float* poi_emb  = (const float*)d_in[6];
    const float* time_emb = (const float*)d_in[7];
    const float* E_t      = (const float*)d_in[8];
    const float* E_d      = (const float*)d_in[9];
    const float* E_dm     = (const float*)d_in[10];
    const float* Remb     = (const float*)d_in[11];
    const float* Wq       = (const float*)d_in[12];
    const float* Wk       = (const float*)d_in[13];
    const float* Wv       = (const float*)d_in[14];
    float* out = (float*)d_out;

    cudaFuncSetAttribute(stan_k1, cudaFuncAttributeMaxDynamicSharedMemorySize,
                         K1_SMEM);
    cudaFuncSetAttribute(stan_k2m, cudaFuncAttributeMaxDynamicSharedMemorySize,
                         K2_SMEM);

    stan_k0<<<128, 128>>>(Wq, Wk);
    stan_k0b<<<250, 256>>>(Remb);
    stan_k0c<<<32, 256>>>(Wv);
    stan_k1<<<BB, 256, K1_SMEM>>>(poi_idx, hour, lat, lon, tmin,
                                  poi_emb, time_emb, E_t, E_d);
    stan_k2m<<<dim3(8, BB / 2), 256, K2_SMEM>>>(poi_idx, lat, lon, cent, E_dm, out);
}

// round 17
// speedup vs baseline: 2.3509x; 1.2280x over previous
#include <cuda_runtime.h>
#include <cuda_bf16.h>
#include <math.h>
#include <cstdint>

// Input order:
// 0 poi_idx(i32 B*N) 1 hour_of_week(i32 B*N) 2 lat 3 lon 4 t_min (f32 B*N)
// 5 region_centroids(R*2) 6 poi_emb((N_POIS+1)*D) 7 time_emb(169*D)
// 8 E_t(64) 9 E_d(64) 10 E_d_match(64) 11 region_emb(R*D) 12 Wq 13 Wk 14 Wv (D*D)
// output: f32 (B, R) = (1024, 1000)

#define BB 1024
#define NN 50
#define RR 1000
#define DD 128
#define DEG2RADF 0.017453292519943295f
#define INV_SQRT_D 0.08838834764831845f   // 1/sqrt(128)

// scratch
__device__ uint32_t g_Sb[BB * NN * 64];   // S bf16x2, [b][n][d/2]
__device__ uint32_t g_Rb[RR * 64];        // Remb bf16x2, [r][d/2]
__device__ uint32_t g_Mb[DD * 64];        // M bf16x2, [bcol][a/2]
__device__ uint32_t g_Wvb[DD * 64];       // Wv bf16x2, [d][a/2]
__device__ float    g_bias[(size_t)BB * 52 * 1024];  // [b][n(52)][r(1024)]

__device__ __forceinline__ uint32_t f2bf2(float2 v) {
    uint32_t r;
    asm("cvt.rn.bf16x2.f32 %0, %1, %2;" : "=r"(r) : "f"(v.y), "f"(v.x));
    return r;
}
__device__ __forceinline__ uint32_t smem_u32(const void* p) {
    uint32_t a;
    asm("{ .reg .u64 t; cvta.to.shared.u64 t, %1; cvt.u32.u64 %0, t; }" : "=r"(a) : "l"(p));
    return a;
}

__device__ __forceinline__ float interp64(const float* t, float x) {
    x = fminf(fmaxf(x, 0.0f), 62.999996f);
    int k = (int)x;
    float f = x - (float)k;
    return t[k] + f * (t[k + 1] - t[k]);
}

// sin(x) for |x| < 0.01 rad: x - x^3/6
__device__ __forceinline__ float sinp(float x) {
    float x2 = x * x;
    return x * fmaf(x2, -0.16666667f, 1.0f);
}

// haversine, asin series (all distances used clipped to <=200km)
__device__ __forceinline__ float hav_km(float dlatr, float dlonr, float cc) {
    float s1 = sinp(0.5f * dlatr);
    float s2 = sinp(0.5f * dlonr);
    float a = fmaf(s1, s1, cc * s2 * s2);
    a = fminf(a, 1.0f);
    float w = sqrtf(a);
    return w * fmaf(2123.6667f, a, 12742.0f);
}

// ---------------- warp MMA helpers (legacy mma.sync, plain sm_103) --------

__device__ __forceinline__ void ldsm_x4(uint32_t addr, uint32_t& r0, uint32_t& r1,
                                        uint32_t& r2, uint32_t& r3) {
    asm volatile("ldmatrix.sync.aligned.m8n8.x4.shared.b16 {%0,%1,%2,%3}, [%4];"
                 : "=r"(r0), "=r"(r1), "=r"(r2), "=r"(r3) : "r"(addr));
}
__device__ __forceinline__ void ldsm_x2(uint32_t addr, uint32_t& r0, uint32_t& r1) {
    asm volatile("ldmatrix.sync.aligned.m8n8.x2.shared.b16 {%0,%1}, [%2];"
                 : "=r"(r0), "=r"(r1) : "r"(addr));
}
__device__ __forceinline__ void ldsm_x2t(uint32_t addr, uint32_t& r0, uint32_t& r1) {
    asm volatile("ldmatrix.sync.aligned.m8n8.x2.trans.shared.b16 {%0,%1}, [%2];"
                 : "=r"(r0), "=r"(r1) : "r"(addr));
}
__device__ __forceinline__ void mma16816(float* d, uint32_t a0, uint32_t a1,
                                         uint32_t a2, uint32_t a3,
                                         uint32_t b0, uint32_t b1) {
    asm volatile(
        "mma.sync.aligned.m16n8k16.row.col.f32.bf16.bf16.f32 "
        "{%0,%1,%2,%3}, {%4,%5,%6,%7}, {%8,%9}, {%0,%1,%2,%3};"
        : "+f"(d[0]), "+f"(d[1]), "+f"(d[2]), "+f"(d[3])
        : "r"(a0), "r"(a1), "r"(a2), "r"(a3), "r"(b0), "r"(b1));
}

// ---------------- Kernel 0 family: precompute bf16 operands --------------

__global__ void stan_k0(const float* __restrict__ Wq, const float* __restrict__ Wk) {
    __shared__ float col[128];
    int bcol = blockIdx.x;    // 0..127
    int a = threadIdx.x;      // 0..127
    float s0 = 0.f, s1 = 0.f, s2 = 0.f, s3 = 0.f;
#pragma unroll
    for (int j = 0; j < 128; j += 4) {
        s0 = fmaf(__ldg(&Wq[(j + 0) * 128 + a]), __ldg(&Wk[(j + 0) * 128 + bcol]), s0);
        s1 = fmaf(__ldg(&Wq[(j + 1) * 128 + a]), __ldg(&Wk[(j + 1) * 128 + bcol]), s1);
        s2 = fmaf(__ldg(&Wq[(j + 2) * 128 + a]), __ldg(&Wk[(j + 2) * 128 + bcol]), s2);
        s3 = fmaf(__ldg(&Wq[(j + 3) * 128 + a]), __ldg(&Wk[(j + 3) * 128 + bcol]), s3);
    }
    col[a] = (s0 + s1) + (s2 + s3);
    __syncthreads();
    if (a < 64)
        g_Mb[bcol * 64 + a] = f2bf2(make_float2(col[2 * a], col[2 * a + 1]));
}

__global__ void stan_k0b(const float* __restrict__ Remb) {
    int i = blockIdx.x * 256 + threadIdx.x;
    if (i < RR * 64) {
        float2 v = ((const float2*)Remb)[i];
        g_Rb[i] = f2bf2(v);
    }
}

__global__ void stan_k0c(const float* __restrict__ Wv) {
    int i = blockIdx.x * 256 + threadIdx.x;
    if (i < DD * 64) {
        float2 v = ((const float2*)Wv)[i];
        g_Wvb[i] = f2bf2(v);
    }
}

// ---------------- Kernel 1b: bias_match table [b][n][r] fp32 --------------
// thread = one r (grid.x covers 1024 r incl. pad), loops n = 0..49.
// pad-n rows get -1e30 (mask folded in). Writes coalesced across r.

__global__ void __launch_bounds__(256)
stan_k1b(const int* __restrict__ poi_idx, const float* __restrict__ lat,
         const float* __restrict__ lon, const float* __restrict__ cent,
         const float* __restrict__ E_dm) {
    __shared__ float slat[52], slon[52], scos[52], sval[52], Edm[64];
    const int b = blockIdx.y;
    const int t = threadIdx.x;
    if (t < 52) {
        if (t < 50) {
            sval[t] = (poi_idx[b * 50 + t] < 0) ? 0.0f : 1.0f;
            float la = lat[b * 50 + t] * DEG2RADF;
            float lo = lon[b * 50 + t] * DEG2RADF;
            slat[t] = la; slon[t] = lo; scos[t] = cosf(la);
        } else { sval[t] = 0.0f; slat[t] = 0.0f; slon[t] = 0.0f; scos[t] = 1.0f; }
    }
    if (t >= 64 && t < 128) Edm[t - 64] = E_dm[t - 64];
    __syncthreads();

    const int r = blockIdx.x * 256 + t;          // 0..1023
    const int rc = (r > 999) ? 999 : r;
    float cl = cent[2 * rc] * DEG2RADF;
    float co = cent[2 * rc + 1] * DEG2RADF;
    float cc = cosf(cl);
    float* outp = g_bias + (((size_t)b * 52) << 10) + r;
#pragma unroll 2
    for (int n = 0; n < 50; n++) {
        float bias = -1.0e30f;
        if (sval[n] != 0.0f) {
            float dd = hav_km(slat[n] - cl, slon[n] - co, cc * scos[n]);
            bias = interp64(Edm, dd * 0.315f);
        }
        outp[n << 10] = bias;
    }
}

// ---------------- Kernel 1: tensor-core attention per batch ---------------

#define XB_O 0
#define WB_O 17408
#define YB_O 52224
#define PF_O 69632
#define PB_O 87040
#define SC_O 96256
#define K1_SMEM (SC_O + 2304)

__global__ void __launch_bounds__(256, 2)
stan_k1(const int* __restrict__ poi_idx, const int* __restrict__ hour,
        const float* __restrict__ lat, const float* __restrict__ lon,
        const float* __restrict__ tmin,
        const float* __restrict__ poi_emb, const float* __restrict__ time_emb,
        const float* __restrict__ E_t, const float* __restrict__ E_d) {
    extern __shared__ char smr[];
    uint32_t sb = smem_u32(smr);
    float* PF   = (float*)(smr + PF_O);
    float* SC   = (float*)(smr + SC_O);
    float* Et     = SC;
    float* Ed     = SC + 64;
    float* tmin_s = SC + 128;
    float* latr   = SC + 192;
    float* lonr   = SC + 256;
    float* coslat = SC + 320;
    float* validf = SC + 384;
    int*   psafe  = (int*)(SC + 448);
    int*   hsafe  = (int*)(SC + 512);

    const int b = blockIdx.x;
    const int t = threadIdx.x;
    const int w = t >> 5, lane = t & 31;
    const int mrow = 16 * (w & 3);
    const int nh = w >> 2;
    const int g = lane >> 2, qp = lane & 3;

    if (t < 64) {
        if (t < 50) {
            int pi = poi_idx[b * 50 + t];
            bool pad = pi < 0;
            psafe[t] = pad ? 50000 : pi;
            hsafe[t] = pad ? 0 : hour[b * 50 + t];
            validf[t] = pad ? 0.0f : 1.0f;
            float la = lat[b * 50 + t] * DEG2RADF;
            float lo = lon[b * 50 + t] * DEG2RADF;
            latr[t] = la; lonr[t] = lo;
            coslat[t] = cosf(la);
            tmin_s[t] = tmin[b * 50 + t];
        } else {
            psafe[t] = 50000; hsafe[t] = 0; validf[t] = 0.0f;
            latr[t] = 0.0f; lonr[t] = 0.0f; coslat[t] = 1.0f; tmin_s[t] = 0.0f;
        }
    }
    if (t >= 64 && t < 128) { Et[t - 64] = E_t[t - 64]; Ed[t - 64] = E_d[t - 64]; }
    for (int i = t; i < 128 * 64; i += 256) {
        int row = i >> 6, cw = i & 63;
        *(uint32_t*)(smr + WB_O + row * 272 + cw * 4) = g_Mb[i];
    }
    __syncthreads();

    for (int i = t; i < 50 * 64; i += 256) {
        int n = i >> 6, dw = i & 63;
        float2 p = *(const float2*)(poi_emb + (size_t)psafe[n] * 128 + 2 * dw);
        float2 q = *(const float2*)(time_emb + (size_t)hsafe[n] * 128 + 2 * dw);
        *(uint32_t*)(smr + XB_O + n * 272 + dw * 4) =
            f2bf2(make_float2(p.x + q.x, p.y + q.y));
    }
    for (int i = t; i < 14 * 64; i += 256) {
        int n = 50 + (i >> 6), dw = i & 63;
        *(uint32_t*)(smr + XB_O + n * 272 + dw * 4) = 0u;
    }
    __syncthreads();

    // ---- MMA1: Y = x M^T ----
    {
        float d1[8][4];
#pragma unroll
        for (int nt = 0; nt < 8; nt++)
#pragma unroll
            for (int u = 0; u < 4; u++) d1[nt][u] = 0.0f;
        uint32_t aa = sb + XB_O + (mrow + (lane & 15)) * 272 + ((lane >> 4) << 4);
        uint32_t ba = sb + WB_O + ((nh << 6) + (lane & 7)) * 272 + (((lane >> 3) & 1) << 4);
#pragma unroll
        for (int ks = 0; ks < 8; ks++) {
            uint32_t a0, a1, a2, a3;
            ldsm_x4(aa + ks * 32, a0, a1, a2, a3);
#pragma unroll
            for (int nt = 0; nt < 8; nt++) {
                uint32_t b0, b1;
                ldsm_x2(ba + nt * 2176 + ks * 32, b0, b1);
                mma16816(d1[nt], a0, a1, a2, a3, b0, b1);
            }
        }
#pragma unroll
        for (int nt = 0; nt < 8; nt++)
#pragma unroll
            for (int rs = 0; rs < 2; rs++) {
                int row = mrow + g + 8 * rs;
                int word = (nh << 5) + 4 * nt + qp;
                *(uint32_t*)(smr + YB_O + row * 272 + word * 4) =
                    f2bf2(make_float2(d1[nt][2 * rs], d1[nt][2 * rs + 1]));
            }
    }
    __syncthreads();

    // ---- MMA2: scores = Y x^T -> PF f32 ----
    {
        float d2[4][4];
#pragma unroll
        for (int nt = 0; nt < 4; nt++)
#pragma unroll
            for (int u = 0; u < 4; u++) d2[nt][u] = 0.0f;
        uint32_t aa = sb + YB_O + (mrow + (lane & 15)) * 272 + ((lane >> 4) << 4);
        uint32_t ba = sb + XB_O + ((nh << 5) + (lane & 7)) * 272 + (((lane >> 3) & 1) << 4);
#pragma unroll
        for (int ks = 0; ks < 8; ks++) {
            uint32_t a0, a1, a2, a3;
            ldsm_x4(aa + ks * 32, a0, a1, a2, a3);
#pragma unroll
            for (int nt = 0; nt < 4; nt++) {
                uint32_t b0, b1;
                ldsm_x2(ba + nt * 2176 + ks * 32, b0, b1);
                mma16816(d2[nt], a0, a1, a2, a3, b0, b1);
            }
        }
#pragma unroll
        for (int nt = 0; nt < 4; nt++)
#pragma unroll
            for (int rs = 0; rs < 2; rs++) {
                int row = mrow + g + 8 * rs;
                int col = (nh << 5) + 8 * nt + 2 * qp;
                *(float2*)(PF + row * 68 + col) =
                    make_float2(d2[nt][2 * rs], d2[nt][2 * rs + 1]);
            }
    }
    for (int i = t; i < 128 * 64; i += 256) {
        int row = i >> 6, cw = i & 63;
        *(uint32_t*)(smr + WB_O + row * 272 + cw * 4) = g_Wvb[i];
    }
    __syncthreads();

    // ---- bias + mask epilogue on PF ----
    for (int q = t; q < 2500; q += 256) {
        int n = q / 50, m = q - n * 50;
        float dotv = PF[n * 68 + m];
        float vm = validf[m];
        float vp = validf[n] * vm;
        float dtm = fabsf(tmin_s[n] - tmin_s[m]) * vp;
        float dd = hav_km(latr[m] - latr[n], lonr[m] - lonr[n],
                          coslat[n] * coslat[m]) * vp;
        float s = dotv * INV_SQRT_D
                + interp64(Et, fminf(dtm, 10080.0f) * 0.00625f)
                + interp64(Ed, fminf(dd, 200.0f) * 0.315f);
        PF[n * 68 + m] = (vm != 0.0f) ? s : -1.0e30f;
    }
    __syncthreads();

    // ---- row softmax ----
    if (t < 50) {
        float mx = -3.0e38f;
#pragma unroll
        for (int m = 0; m < 50; m++) mx = fmaxf(mx, PF[t * 68 + m]);
        if (mx <= -9.0e29f) {
            for (int m = 0; m < 50; m++) PF[t * 68 + m] = 0.0f;
        } else {
            float sum = 0.0f;
#pragma unroll
            for (int m = 0; m < 50; m++) {
                float e = __expf(PF[t * 68 + m] - mx);
                PF[t * 68 + m] = e; sum += e;
            }
            float inv = 1.0f / sum;
#pragma unroll
            for (int m = 0; m < 50; m++) PF[t * 68 + m] *= inv;
        }
    }
    __syncthreads();

    // ---- MMA3: V = x Wv^T -> VB (overlay YB) bf16 ----
    {
        float d3[8][4];
#pragma unroll
        for (int nt = 0; nt < 8; nt++)
#pragma unroll
            for (int u = 0; u < 4; u++) d3[nt][u] = 0.0f;
        uint32_t aa = sb + XB_O + (mrow + (lane & 15)) * 272 + ((lane >> 4) << 4);
        uint32_t ba = sb + WB_O + ((nh << 6) + (lane & 7)) * 272 + (((lane >> 3) & 1) << 4);
#pragma unroll
        for (int ks = 0; ks < 8; ks++) {
            uint32_t a0, a1, a2, a3;
            ldsm_x4(aa + ks * 32, a0, a1, a2, a3);
#pragma unroll
            for (int nt = 0; nt < 8; nt++) {
                uint32_t b0, b1;
                ldsm_x2(ba + nt * 2176 + ks * 32, b0, b1);
                mma16816(d3[nt], a0, a1, a2, a3, b0, b1);
            }
        }
        __syncthreads();
#pragma unroll
        for (int nt = 0; nt < 8; nt++)
#pragma unroll
            for (int rs = 0; rs < 2; rs++) {
                int row = mrow + g + 8 * rs;
                int word = (nh << 5) + 4 * nt + qp;
                *(uint32_t*)(smr + YB_O + row * 272 + word * 4) =
                    f2bf2(make_float2(d3[nt][2 * rs], d3[nt][2 * rs + 1]));
            }
    }
    for (int i = t; i < 64 * 32; i += 256) {
        int row = i >> 5, cw = i & 31;
        float2 v = *(float2*)(PF + row * 68 + 2 * cw);
        *(uint32_t*)(smr + PB_O + row * 144 + cw * 4) = f2bf2(v);
    }
    __syncthreads();

    // ---- MMA4: S = attn @ V, B via ldmatrix.trans on V[m][d] ----
    {
        float d4[8][4];
#pragma unroll
        for (int nt = 0; nt < 8; nt++)
#pragma unroll
            for (int u = 0; u < 4; u++) d4[nt][u] = 0.0f;
        uint32_t aa = sb + PB_O + (mrow + (lane & 15)) * 144 + ((lane >> 4) << 4);
#pragma unroll
        for (int ks = 0; ks < 4; ks++) {
            uint32_t a0, a1, a2, a3;
            ldsm_x4(aa + ks * 32, a0, a1, a2, a3);
            uint32_t brow = sb + YB_O + (16 * ks + (lane & 15)) * 272;
#pragma unroll
            for (int nt = 0; nt < 8; nt++) {
                uint32_t b0, b1;
                ldsm_x2t(brow + ((nh << 6) + 8 * nt) * 2, b0, b1);
                mma16816(d4[nt], a0, a1, a2, a3, b0, b1);
            }
        }
#pragma unroll
        for (int nt = 0; nt < 8; nt++)
#pragma unroll
            for (int rs = 0; rs < 2; rs++) {
                int n = mrow + g + 8 * rs;
                if (n < 50) {
                    int word = (nh << 5) + 4 * nt + qp;
                    g_Sb[((size_t)b * 50 + n) * 64 + word] =
                        f2bf2(make_float2(d4[nt][2 * rs], d4[nt][2 * rs + 1]));
                }
            }
    }
}

// ---------------- Kernel 2: bf16 GEMM + bias-table softmax ----------------
// A = Remb chunk [128 x 128], B = S for 2 batches (n rows 0-49 / 64-113).
// Bias (incl. mask) read from g_bias fp32. d[7]/d[15] (cols n>=56) unused.

#define K2_A   0
#define K2_B   34816
#define K2_SMEM 69632

__global__ void __launch_bounds__(256, 3)
stan_k2m(float* __restrict__ out) {
    extern __shared__ char smr[];
    uint32_t sb = smem_u32(smr);
    const int bp = blockIdx.y;           // batch pair
    const int rbase = blockIdx.x * 128;
    const int t = threadIdx.x;
    const int w = t >> 5, lane = t & 31;

    // A tile
    for (int p = t; p < 8192; p += 256) {
        int row = p >> 6, pi = p & 63;
        int r = rbase + row; if (r > 999) r = 999;
        *(uint32_t*)(smr + K2_A + row * 272 + pi * 4) = g_Rb[r * 64 + pi];
    }
    // B tile (rows 50-63 / 114-127 zero)
    for (int p = t; p < 8192; p += 256) {
        int row = p >> 6, pi = p & 63;
        int h = row >> 6, nn = row & 63;
        uint32_t v = (nn < 50) ? g_Sb[((size_t)(2 * bp + h) * 50 + nn) * 64 + pi] : 0u;
        *(uint32_t*)(smr + K2_B + row * 272 + pi * 4) = v;
    }
    __syncthreads();

    const uint32_t aaddr = sb + K2_A + (16 * w + (lane & 15)) * 272 + ((lane >> 4) << 4);
    // x4 B: lanes 0-15 -> tile 2p (k-lo/k-hi), lanes 16-31 -> tile 2p+1
    const uint32_t baddr = sb + K2_B + (lane >> 4) * 2176 + (lane & 7) * 272
                         + (((lane >> 3) & 1) << 4);

    float d[16][4];
#pragma unroll
    for (int nt = 0; nt < 16; nt++)
#pragma unroll
        for (int u = 0; u < 4; u++) d[nt][u] = 0.0f;

#pragma unroll
    for (int ks = 0; ks < 8; ks++) {
        uint32_t a0, a1, a2, a3;
        ldsm_x4(aaddr + ks * 32, a0, a1, a2, a3);
#pragma unroll
        for (int p = 0; p < 8; p++) {
            uint32_t b0, b1, b2, b3;
            ldsm_x4(baddr + p * 4352 + ks * 32, b0, b1, b2, b3);
            mma16816(d[2 * p], a0, a1, a2, a3, b0, b1);
            if ((p & 3) != 3)   // skip nt = 7, 15 (cols never read)
                mma16816(d[2 * p + 1], a0, a1, a2, a3, b2, b3);
        }
    }

    // epilogue: bias from table + exp; quad butterfly reduce over n
    const int g = lane >> 2, qp = lane & 3;
    const float* gb = g_bias + (((size_t)(2 * bp) * 52) << 10);
#pragma unroll
    for (int rs = 0; rs < 2; rs++) {
        int r = rbase + 16 * w + g + 8 * rs;
        const float* gb0 = gb + r;
        const float* gb1 = gb0 + (52 << 10);
        float den0 = 0.f, num0 = 0.f, den1 = 0.f, num1 = 0.f;
#pragma unroll
        for (int nt = 0; nt < 16; nt++) {
            int nl = nt & 7;
            if (nl == 7) continue;
            const float* gbh = (nt < 8) ? gb0 : gb1;
#pragma unroll
            for (int u = 0; u < 2; u++) {
                int nn = 8 * nl + 2 * qp + u;
                float bias;
                if (nl == 6) {
                    bias = -1.0e30f;
                    if (qp == 0) bias = __ldg(gbh + (nn << 10));
                } else {
                    bias = __ldg(gbh + (nn << 10));
                }
                float v = d[nt][2 * rs + u];
                float s = fmaf(v, INV_SQRT_D, bias);
                float e = __expf(s);       // masked/pad -> exactly 0
                if (nt < 8) { den0 += e; num0 = fmaf(e, s, num0); }
                else        { den1 += e; num1 = fmaf(e, s, num1); }
            }
        }
#pragma unroll
        for (int off = 1; off <= 2; off <<= 1) {
            den0 += __shfl_xor_sync(0xffffffffu, den0, off);
            num0 += __shfl_xor_sync(0xffffffffu, num0, off);
            den1 += __shfl_xor_sync(0xffffffffu, den1, off);
            num1 += __shfl_xor_sync(0xffffffffu, num1, off);
        }
        if (qp == 0 && r < RR) {
            out[(size_t)(2 * bp + 0) * RR + r] = (den0 > 0.f) ? (num0 / den0) : 0.f;
            out[(size_t)(2 * bp + 1) * RR + r] = (den1 > 0.f) ? (num1 / den1) : 0.f;
        }
    }
}

// ---------------- launcher ----------------

extern "C" void kernel_launch(void* const* d_in, const int* in_sizes, int n_in,
                              void* d_out, int out_size) {
    const int*   poi_idx  = (const int*)d_in[0];
    const int*   hour     = (const int*)d_in[1];
    const float* lat      = (const float*)d_in[2];
    const float* lon      = (const float*)d_in[3];
    const float* tmin     = (const float*)d_in[4];
    const float* cent     = (const float*)d_in[5];
    const float* poi_emb  = (const float*)d_in[6];
    const float* time_emb = (const float*)d_in[7];
    const float* E_t      = (const float*)d_in[8];
    const float* E_d      = (const float*)d_in[9];
    const float* E_dm     = (const float*)d_in[10];
    const float* Remb     = (const float*)d_in[11];
    const float* Wq       = (const float*)d_in[12];
    const float* Wk       = (const float*)d_in[13];
    const float* Wv       = (const float*)d_in[14];
    float* out = (float*)d_out;

    cudaFuncSetAttribute(stan_k1, cudaFuncAttributeMaxDynamicSharedMemorySize,
                         K1_SMEM);
    cudaFuncSetAttribute(stan_k2m, cudaFuncAttributeMaxDynamicSharedMemorySize,
                         K2_SMEM);

    stan_k0<<<128, 128>>>(Wq, Wk);
    stan_k0b<<<250, 256>>>(Remb);
    stan_k0c<<<32, 256>>>(Wv);
    stan_k1b<<<dim3(4, BB), 256>>>(poi_idx, lat, lon, cent, E_dm);
    stan_k1<<<BB, 256, K1_SMEM>>>(poi_idx, hour, lat, lon, tmin,
                                  poi_emb, time_emb, E_t, E_d);
    stan_k2m<<<dim3(8, BB / 2), 256, K2_SMEM>>>(out);
}